// round 2
// baseline (speedup 1.0000x reference)
#include <cuda_runtime.h>

#define N_   8
#define D_   64
#define H_   64
#define W_   64
#define HW_  4096
#define CHW  (D_*HW_)   /* 262144 */
#define KK   25

// Scratch (static __device__ allocation — allowed; no runtime allocs)
__device__ int   g_cnt[2][N_];
__device__ float g_inv[N_];
__device__ float g_w[N_*HW_*KK];   // per-pixel normalized window weights (delta at k=12 if zero_mass)

__global__ void zero_cnt_kernel() {
    int t = threadIdx.x;
    if (t < 2*N_) ((int*)g_cnt)[t] = 0;
}

// Count nonzeros of cur (arr=0) and prev (arr=1) per batch.
__global__ void count_kernel(const float* __restrict__ cur, const float* __restrict__ prev) {
    int arr = blockIdx.y;
    int n   = blockIdx.z;
    const float4* p = (const float4*)((arr == 0 ? cur : prev) + (size_t)n * CHW);
    const int nv = CHW / 4;  // 65536 float4
    int cnt = 0;
    for (int i = blockIdx.x * blockDim.x + threadIdx.x; i < nv; i += gridDim.x * blockDim.x) {
        float4 v = p[i];
        cnt += (v.x != 0.f) + (v.y != 0.f) + (v.z != 0.f) + (v.w != 0.f);
    }
    #pragma unroll
    for (int o = 16; o; o >>= 1) cnt += __shfl_xor_sync(0xffffffffu, cnt, o);
    __shared__ int ws[8];
    int lane = threadIdx.x & 31, wid = threadIdx.x >> 5;
    if (lane == 0) ws[wid] = cnt;
    __syncthreads();
    if (wid == 0) {
        int c = (lane < (int)(blockDim.x >> 5)) ? ws[lane] : 0;
        #pragma unroll
        for (int o = 4; o; o >>= 1) c += __shfl_xor_sync(0xffffffffu, c, o);
        if (lane == 0) atomicAdd(&g_cnt[arr][n], c);
    }
}

__global__ void finalize_kernel() {
    int t = threadIdx.x;
    if (t < N_) {
        float a = (float)g_cnt[0][t] + 1e-8f;
        float b = (float)g_cnt[1][t] + 1e-8f;
        g_inv[t] = 1.0f / (a * b);
    }
}

// One CTA per (row y, batch n). smem: cur row [d][x] (16KB) + 5 prev rows (80KB).
// 4 threads per pixel x split the 25 window taps; mass combined via shfl.
__global__ void weights_kernel(const float* __restrict__ cur, const float* __restrict__ prev) {
    extern __shared__ float sm[];
    float* cur_s  = sm;          // idx = d*64 + x
    float* prev_s = sm + HW_;    // idx = r*4096 + d*64 + x  (r = dy+2, rows clamped)
    const int y = blockIdx.x, n = blockIdx.y;
    const int t = threadIdx.x;
    const float* curb  = cur  + (size_t)n * CHW;
    const float* prevb = prev + (size_t)n * CHW;

    for (int i = t; i < HW_; i += 256) {
        int d = i >> 6, x = i & 63;
        cur_s[i] = curb[d * HW_ + y * W_ + x];
    }
    for (int i = t; i < 5 * HW_; i += 256) {
        int r = i >> 12;
        int rem = i & 4095;
        int d = rem >> 6, x = rem & 63;
        int yy = y - 2 + r; yy = yy < 0 ? 0 : (yy > H_-1 ? H_-1 : yy);
        prev_s[i] = prevb[d * HW_ + yy * W_ + x];
    }
    __syncthreads();

    const int x = t >> 2, q = t & 3;   // 4 lanes (same warp, adjacent) share a pixel

    int   base[7];
    float live[7];
    #pragma unroll
    for (int j = 0; j < 7; j++) {
        int k  = q + 4 * j;
        int kk = k < KK ? k : 12;           // dummy (dead) slot for q!=0, j==6
        int dy = kk / 5 - 2, dx = kk % 5 - 2;
        int py = y + dy, px = x + dx;
        bool ok = (k < KK) && py >= 0 && py < H_ && px >= 0 && px < W_;
        int pxc = px < 0 ? 0 : (px > W_-1 ? W_-1 : px);
        base[j] = (dy + 2) * HW_ + pxc;
        live[j] = ok ? 1.0f : 0.0f;
    }

    float acc[7] = {0.f,0.f,0.f,0.f,0.f,0.f,0.f};
    #pragma unroll 4
    for (int d = 0; d < D_; d++) {
        float c  = cur_s[d * 64 + x];
        int  off = d * 64;
        #pragma unroll
        for (int j = 0; j < 7; j++) acc[j] += c * prev_s[base[j] + off];
    }

    float m = 0.f;
    #pragma unroll
    for (int j = 0; j < 7; j++) {
        acc[j] = fmaxf(acc[j], 0.f) * live[j];   // coef (unscaled — scale cancels in w)
        m += acc[j];
    }
    m += __shfl_xor_sync(0xffffffffu, m, 1);
    m += __shfl_xor_sync(0xffffffffu, m, 2);

    const float inv  = g_inv[n];
    const bool  zero = fabsf(m * inv) < 1e-7f;   // reference threshold (scaled domain)
    const float invm = zero ? 0.f : 1.0f / m;

    const size_t wbase = ((size_t)(n * HW_ + y * W_ + x)) * KK;
    #pragma unroll
    for (int j = 0; j < 7; j++) {
        int k = q + 4 * j;
        if (k < KK) {
            float wv = zero ? (k == 12 ? 1.0f : 0.0f) : acc[j] * invm;
            g_w[wbase + k] = wv;
        }
    }
}

// One CTA per (row y, batch n). smem: 5 prev_mem rows (80KB).
// Thread handles pixel x for a 16-wide d chunk; 25 weights cached in registers.
__global__ void output_kernel(const float* __restrict__ pm, float* __restrict__ out) {
    extern __shared__ float pm_s[];  // [5][64][64]: idx = r*4096 + d*64 + x
    const int y = blockIdx.x, n = blockIdx.y;
    const int t = threadIdx.x;
    const float* pmb = pm + (size_t)n * CHW;

    for (int i = t; i < 5 * HW_; i += 256) {
        int r = i >> 12;
        int rem = i & 4095;
        int d = rem >> 6, x = rem & 63;
        int yy = y - 2 + r; yy = yy < 0 ? 0 : (yy > H_-1 ? H_-1 : yy);
        pm_s[i] = pmb[d * HW_ + yy * W_ + x];
    }
    __syncthreads();

    const int x = t & 63, dg = t >> 6;

    float wr[KK];
    const size_t wbase = ((size_t)(n * HW_ + y * W_ + x)) * KK;
    #pragma unroll
    for (int k = 0; k < KK; k++) wr[k] = g_w[wbase + k];

    int sb[KK];
    #pragma unroll
    for (int k = 0; k < KK; k++) {
        int dy = k / 5 - 2, dx = k % 5 - 2;
        int px = x + dx; px = px < 0 ? 0 : (px > W_-1 ? W_-1 : px);
        sb[k] = (dy + 2) * HW_ + px;
    }

    const int d0 = dg * 16;
    for (int d = d0; d < d0 + 16; d++) {
        float s = 0.f;
        const int off = d * 64;
        #pragma unroll
        for (int k = 0; k < KK; k++) s += wr[k] * pm_s[sb[k] + off];
        out[(size_t)n * CHW + d * HW_ + y * W_ + x] = s;
    }
}

extern "C" void kernel_launch(void* const* d_in, const int* in_sizes, int n_in,
                              void* d_out, int out_size) {
    const float* cur  = (const float*)d_in[0];
    const float* prev = (const float*)d_in[1];
    const float* pm   = (const float*)d_in[2];
    float* out = (float*)d_out;
    (void)in_sizes; (void)n_in; (void)out_size;

    // >48KB dynamic smem opt-in (idempotent; not a stream op, safe under capture)
    cudaFuncSetAttribute(weights_kernel, cudaFuncAttributeMaxDynamicSharedMemorySize, 6 * HW_ * 4);
    cudaFuncSetAttribute(output_kernel,  cudaFuncAttributeMaxDynamicSharedMemorySize, 5 * HW_ * 4);

    zero_cnt_kernel<<<1, 32>>>();
    count_kernel<<<dim3(64, 2, N_), 256>>>(cur, prev);
    finalize_kernel<<<1, 32>>>();
    weights_kernel<<<dim3(H_, N_), 256, 6 * HW_ * 4>>>(cur, prev);
    output_kernel<<<dim3(H_, N_), 256, 5 * HW_ * 4>>>(pm, out);
}